// round 3
// baseline (speedup 1.0000x reference)
#include <cuda_runtime.h>
#include <math.h>

#define H_IN   14
#define W_IN   14
#define HP     12
#define WP     12
#define ISZ    144
#define OSZ    16
#define NPOS   1152
#define RST    145          // z/rp row stride: odd -> conflict-free column access
#define EPSF   1e-9f

__global__ void __launch_bounds__(512, 1)
capsconv_em_kernel(const float* __restrict__ pose_in,   // [8,14,14,256]
                   const float* __restrict__ act_in,    // [8,14,14,16]
                   const float* __restrict__ w,         // [144,16,16]
                   const float* __restrict__ beta_v,    // [16]
                   const float* __restrict__ beta_a,    // [16]
                   float* __restrict__ out)             // pose[1152*256] ++ act[1152*16]
{
    __shared__ float poseS[ISZ * 16];    // 9216 B
    __shared__ float actS[ISZ];          //  576 B
    __shared__ float zS[OSZ * RST];      // 9280 B  (z, then rr*act in-place)

    const int tid = threadIdx.x;
    const int n   = blockIdx.x;
    const int b   = n / (HP * WP);
    const int rem = n % (HP * WP);
    const int y   = rem / WP;
    const int x   = rem % WP;

    // ---- Stage pose patch + activations into SMEM (coalesced) ----
    for (int idx = tid; idx < ISZ * 4; idx += 512) {
        int i  = idx >> 2;
        int p4 = idx & 3;
        int pos = i >> 4, c = i & 15;
        int ky = pos / 3, kx = pos % 3;
        const float4* src = reinterpret_cast<const float4*>(
            pose_in + ((((b * H_IN) + y + ky) * W_IN + (x + kx)) * 256 + c * 16));
        reinterpret_cast<float4*>(poseS)[i * 4 + p4] = src[p4];
    }
    for (int i = tid; i < ISZ; i += 512) {
        int pos = i >> 4, c = i & 15;
        int ky = pos / 3, kx = pos % 3;
        actS[i] = act_in[(((b * H_IN) + y + ky) * W_IN + (x + kx)) * OSZ + c];
    }
    __syncthreads();

    // ---- rp init for iteration 0: rr uniform 1/16 -> rp[o][i] = act[i]/16 ----
    for (int idx = tid; idx < OSZ * ISZ; idx += 512) {
        int oo = idx / ISZ;
        int i  = idx - oo * ISZ;
        zS[oo * RST + i] = actS[i] * 0.0625f;
    }

    // ---- Thread mapping: warp = o, lane = pr*8 + chunk, i = chunk + 8*ii ----
    const int lane  = tid & 31;
    const int o     = tid >> 5;
    const int pr    = lane >> 3;    // pose row (4 consecutive p dims)
    const int chunk = lane & 7;

    // ---- Vote transform directly into registers ----
    // vt[ii] = pose[i][pr][:] @ w[i][o]   (4 output cols), i = chunk + 8*ii
    float4 vt[18];
    #pragma unroll
    for (int ii = 0; ii < 18; ++ii) {
        const int i = chunk + (ii << 3);
        float4 p = reinterpret_cast<const float4*>(poseS)[i * 4 + pr];
        const float4* wr = reinterpret_cast<const float4*>(w + (i * 16 + o) * 16);
        float4 w0 = wr[0], w1 = wr[1], w2 = wr[2], w3 = wr[3];
        float4 r;
        r.x = fmaf(p.x, w0.x, fmaf(p.y, w1.x, fmaf(p.z, w2.x, p.w * w3.x)));
        r.y = fmaf(p.x, w0.y, fmaf(p.y, w1.y, fmaf(p.z, w2.y, p.w * w3.y)));
        r.z = fmaf(p.x, w0.z, fmaf(p.y, w1.z, fmaf(p.z, w2.z, p.w * w3.z)));
        r.w = fmaf(p.x, w0.w, fmaf(p.y, w1.w, fmaf(p.z, w2.w, p.w * w3.w)));
        vt[ii] = r;
    }
    const float bv = beta_v[o];
    const float ba = beta_a[o];
    const float* rpo = zS + o * RST;
    __syncthreads();   // rp ready

    for (int it = 0; it < 3; ++it) {
        // ---- M-step: single-pass moments over i (registers + rp broadcast) ----
        float m0=0.f,m1=0.f,m2=0.f,m3=0.f;
        float s0=0.f,s1=0.f,s2=0.f,s3=0.f;
        float rs=0.f;
        #pragma unroll
        for (int ii = 0; ii < 18; ++ii) {
            float rp = rpo[chunk + (ii << 3)];
            float4 v = vt[ii];
            float tx = rp * v.x, ty = rp * v.y, tz = rp * v.z, tw = rp * v.w;
            m0 += tx;  s0 = fmaf(tx, v.x, s0);
            m1 += ty;  s1 = fmaf(ty, v.y, s1);
            m2 += tz;  s2 = fmaf(tz, v.z, s2);
            m3 += tw;  s3 = fmaf(tw, v.w, s3);
            rs += rp;
        }
        #pragma unroll
        for (int off = 1; off < 8; off <<= 1) {
            m0 += __shfl_xor_sync(0xffffffffu, m0, off);
            m1 += __shfl_xor_sync(0xffffffffu, m1, off);
            m2 += __shfl_xor_sync(0xffffffffu, m2, off);
            m3 += __shfl_xor_sync(0xffffffffu, m3, off);
            s0 += __shfl_xor_sync(0xffffffffu, s0, off);
            s1 += __shfl_xor_sync(0xffffffffu, s1, off);
            s2 += __shfl_xor_sync(0xffffffffu, s2, off);
            s3 += __shfl_xor_sync(0xffffffffu, s3, off);
            rs += __shfl_xor_sync(0xffffffffu, rs, off);
        }
        const float inv_r = __fdividef(1.0f, rs + EPSF);
        const float me0 = m0 * inv_r, me1 = m1 * inv_r;
        const float me2 = m2 * inv_r, me3 = m3 * inv_r;
        float e0 = fmaf(me0, fmaf(me0, rs, -2.0f * m0), s0);
        float e1 = fmaf(me1, fmaf(me1, rs, -2.0f * m1), s1);
        float e2 = fmaf(me2, fmaf(me2, rs, -2.0f * m2), s2);
        float e3 = fmaf(me3, fmaf(me3, rs, -2.0f * m3), s3);
        float v0 = fmaxf(e0, 0.f) * inv_r, v1 = fmaxf(e1, 0.f) * inv_r;
        float v2 = fmaxf(e2, 0.f) * inv_r, v3 = fmaxf(e3, 0.f) * inv_r;
        float lsum = (__logf(sqrtf(v0) + EPSF) + __logf(sqrtf(v1) + EPSF))
                   + (__logf(sqrtf(v2) + EPSF) + __logf(sqrtf(v3) + EPSF));
        lsum += __shfl_xor_sync(0xffffffffu, lsum, 8);
        lsum += __shfl_xor_sync(0xffffffffu, lsum, 16);  // sum over all 16 p

        const float inv_temp = 1.0f + (float)it;
        const float cost = fmaf(16.0f, bv, lsum) * rs;
        const float a = __fdividef(1.0f, 1.0f + __expf(-inv_temp * (ba - cost)));

        if (it == 2) {
            if (chunk == 0) {
                *reinterpret_cast<float4*>(out + n * 256 + o * 16 + pr * 4) =
                    make_float4(me0, me1, me2, me3);
            }
            if (lane == 0)
                out[NPOS * 256 + n * OSZ + o] = a;
            return;
        }

        const float logact = __logf(a + EPSF);
        // inverse (2*var + eps) for this lane's 4 p dims
        const float iv0 = __fdividef(1.0f, 2.0f * v0 + EPSF);
        const float iv1 = __fdividef(1.0f, 2.0f * v1 + EPSF);
        const float iv2 = __fdividef(1.0f, 2.0f * v2 + EPSF);
        const float iv3 = __fdividef(1.0f, 2.0f * v3 + EPSF);

        // ---- E-step part 1: per-(i,o) log-likelihood from registers ----
        #pragma unroll
        for (int ii = 0; ii < 18; ++ii) {
            float4 v = vt[ii];
            float dx = v.x - me0, dy = v.y - me1;
            float dz = v.z - me2, dw = v.w - me3;
            float acc = dx * dx * iv0;
            acc = fmaf(dy * dy, iv1, acc);
            acc = fmaf(dz * dz, iv2, acc);
            acc = fmaf(dw * dw, iv3, acc);
            acc += __shfl_xor_sync(0xffffffffu, acc, 8);
            acc += __shfl_xor_sync(0xffffffffu, acc, 16);  // sum over all 16 p
            if (pr == 0)
                zS[o * RST + chunk + (ii << 3)] = logact - acc - lsum;
        }
        __syncthreads();   // z ready

        // ---- E-step part 2: softmax over o, fold act -> rp in-place ----
        if (tid < 2 * ISZ) {
            const int i = tid >> 1;
            const int g = tid & 1;
            float zz[8];
            float zmax = -1e30f;
            #pragma unroll
            for (int j = 0; j < 8; ++j) {
                float z = zS[((j << 1) + g) * RST + i];
                zz[j] = z;
                zmax = fmaxf(zmax, z);
            }
            zmax = fmaxf(zmax, __shfl_xor_sync(0xffffffffu, zmax, 1));
            float es = 0.f;
            #pragma unroll
            for (int j = 0; j < 8; ++j) { zz[j] = __expf(zz[j] - zmax); es += zz[j]; }
            es += __shfl_xor_sync(0xffffffffu, es, 1);
            const float f = __fdividef(actS[i], es);   // rp = softmax * act
            #pragma unroll
            for (int j = 0; j < 8; ++j)
                zS[((j << 1) + g) * RST + i] = zz[j] * f;
        }
        __syncthreads();   // rp ready for next M-step
    }
}

extern "C" void kernel_launch(void* const* d_in, const int* in_sizes, int n_in,
                              void* d_out, int out_size)
{
    const float* pose_in = (const float*)d_in[0];
    const float* act_in  = (const float*)d_in[1];
    const float* w       = (const float*)d_in[2];
    const float* bv      = (const float*)d_in[3];
    const float* ba      = (const float*)d_in[4];
    float* out           = (float*)d_out;

    capsconv_em_kernel<<<NPOS, 512>>>(pose_in, act_in, w, bv, ba, out);
}